// round 5
// baseline (speedup 1.0000x reference)
#include <cuda_runtime.h>

// RoIPooling2D (Caffe roi_pool, max) — NHWC gather, batched-load version.
// x [B=2, C=256, H=50, W=50] f32, rois [N,5] f32, out [N, C, 7, 7] f32.
// Bin bounds replicate XLA:GPU arithmetic exactly (div.full.f32, Round 3).
//
// Pipeline:
//   1) transpose_in: x NCHW -> g_xt NHWC ([b][h*w][c])
//   2) gather: grid (N, 2 channel-halves, 2 bin-groups), 256 thr (8 warps).
//      lane = 4 channels (float4), warp = bin. Bin pixel loads issued as an
//      unrolled predicated 4x4 batch -> ~16 LDGs in flight, one L2 latency.

#define POOL_H 7
#define POOL_W 7
#define NBINS  (POOL_H * POOL_W)       // 49
#define SPATIAL_SCALE 0.0625f
#define C_TOT  256
#define HDIM   50
#define WDIM   50
#define HW     (HDIM * WDIM)           // 2500
#define CH     128                     // channels per gather block (half)
#define BIN_SPLIT 2
#define BINS_PER_GRP ((NBINS + BIN_SPLIT - 1) / BIN_SPLIT)   // 25
#define GTHREADS 256
#define NEG_FLT_MAX (-3.402823466e38f)

__device__ float g_xt[2 * HW * C_TOT];  // NHWC scratch, 5.12 MB

__device__ __forceinline__ float div_full(float a, float b) {
    float r;
    asm("div.full.f32 %0, %1, %2;" : "=f"(r) : "f"(a), "f"(b));
    return r;
}

__device__ __forceinline__ float4 fmax4(float4 a, float4 b) {
    return make_float4(fmaxf(a.x, b.x), fmaxf(a.y, b.y),
                       fmaxf(a.z, b.z), fmaxf(a.w, b.w));
}

// ---------------- Kernel 1: NCHW -> NHWC transpose ----------------
__global__ void transpose_in_kernel(const float* __restrict__ x) {
    __shared__ float tile[32][33];
    int b  = blockIdx.z;
    int p0 = blockIdx.x * 32;   // spatial (h*W+w)
    int c0 = blockIdx.y * 32;   // channel
    int tx = threadIdx.x;       // 0..31
    int ty = threadIdx.y;       // 0..7

    #pragma unroll
    for (int k = 0; k < 4; ++k) {
        int c = c0 + ty + k * 8;
        int p = p0 + tx;
        if (p < HW)
            tile[ty + k * 8][tx] = x[((size_t)b * C_TOT + c) * HW + p];
    }
    __syncthreads();
    #pragma unroll
    for (int k = 0; k < 4; ++k) {
        int p = p0 + ty + k * 8;
        int c = c0 + tx;
        if (p < HW)
            g_xt[((size_t)b * HW + p) * C_TOT + c] = tile[tx][ty + k * 8];
    }
}

// ---------------- Kernel 2: fused bounds + batched gather ----------------
__global__ void __launch_bounds__(GTHREADS)
roi_gather_kernel(const float* __restrict__ rois, float* __restrict__ out, int N) {
    __shared__ float s_res[CH * BINS_PER_GRP];   // [c_local][bin_local], 12.8 KB
    __shared__ int   s_hs[POOL_H], s_he[POOL_H], s_ws[POOL_W], s_we[POOL_W];
    __shared__ int   s_b;

    int n    = blockIdx.x;
    int half = blockIdx.y;                       // channel half
    int bin0 = blockIdx.z * BINS_PER_GRP;        // first bin of this group
    int nb   = min(NBINS - bin0, BINS_PER_GRP);  // 25 or 24
    int tid  = threadIdx.x;
    int warp = tid >> 5;
    int lane = tid & 31;

    // --- bounds (exact replica of reference arithmetic, incl. div.full) ---
    if (tid < POOL_H + POOL_W + 1) {
        const float* r = rois + n * 5;
        if (tid == POOL_H + POOL_W) {
            s_b = (int)r[0];
        } else {
            bool is_h = (tid < POOL_H);
            int  i    = is_h ? tid : tid - POOL_H;
            float s1  = rintf(__fmul_rn(r[is_h ? 2 : 1], SPATIAL_SCALE));
            float e1  = rintf(__fmul_rn(r[is_h ? 4 : 3], SPATIAL_SCALE));
            float sz  = fmaxf(__fadd_rn(__fsub_rn(e1, s1), 1.0f), 1.0f);
            float bs  = div_full(sz, is_h ? (float)POOL_H : (float)POOL_W);
            float npx = is_h ? (float)HDIM : (float)WDIM;
            float lo = __fadd_rn(floorf(__fmul_rn((float)i, bs)), s1);
            float hi = __fadd_rn(ceilf(__fmul_rn((float)(i + 1), bs)), s1);
            lo = fminf(fmaxf(lo, 0.0f), npx);
            hi = fminf(fmaxf(hi, 0.0f), npx);
            if (is_h) { s_hs[i] = (int)lo; s_he[i] = (int)hi; }
            else      { s_ws[i] = (int)lo; s_we[i] = (int)hi; }
        }
    }
    __syncthreads();

    // --- gather: warp = bin (within group), lane = 4 channels (float4) ---
    int c4 = half * CH + lane * 4;
    const float* xb = g_xt + (size_t)s_b * (HW * C_TOT) + c4;

    for (int bl = warp; bl < nb; bl += (GTHREADS / 32)) {
        int bin = bin0 + bl;
        int ph = bin / POOL_W;
        int pw = bin - ph * POOL_W;
        int hs = s_hs[ph], he = s_he[ph];
        int ws = s_ws[pw], we = s_we[pw];
        int wh = he - hs, ww = we - ws;
        bool empty = (wh <= 0) || (ww <= 0);

        float4 m = make_float4(NEG_FLT_MAX, NEG_FLT_MAX, NEG_FLT_MAX, NEG_FLT_MAX);
        if (wh <= 4 && ww <= 4) {
            // Batched predicated 4x4 load grid: all LDGs independent/in-flight.
            #pragma unroll
            for (int dh = 0; dh < 4; ++dh) {
                int h = hs + dh;
                bool hv = dh < wh;
                const float* rowp = xb + (size_t)(h * WDIM) * C_TOT;
                #pragma unroll
                for (int dw = 0; dw < 4; ++dw) {
                    int w = ws + dw;
                    if (hv && dw < ww) {
                        float4 v = __ldg(reinterpret_cast<const float4*>(
                            rowp + (size_t)w * C_TOT));
                        m = fmax4(m, v);
                    }
                }
            }
        } else {
            // Fallback (never hit with this data shape, kept for safety).
            for (int h = hs; h < he; ++h) {
                const float* rowp = xb + (size_t)(h * WDIM) * C_TOT;
                for (int w = ws; w < we; ++w) {
                    float4 v = __ldg(reinterpret_cast<const float4*>(
                        rowp + (size_t)w * C_TOT));
                    m = fmax4(m, v);
                }
            }
        }
        if (empty) m = make_float4(0.f, 0.f, 0.f, 0.f);

        int cl = lane * 4;
        s_res[(cl + 0) * BINS_PER_GRP + bl] = m.x;
        s_res[(cl + 1) * BINS_PER_GRP + bl] = m.y;
        s_res[(cl + 2) * BINS_PER_GRP + bl] = m.z;
        s_res[(cl + 3) * BINS_PER_GRP + bl] = m.w;
    }
    __syncthreads();

    // --- write out: out[n][c][bin], contiguous runs of nb floats per channel ---
    float* obase = out + (size_t)n * (C_TOT * NBINS) + (size_t)half * (CH * NBINS) + bin0;
    int total = CH * nb;
    for (int i = tid; i < total; i += GTHREADS) {
        int c  = i / nb;
        int bl = i - c * nb;
        obase[c * NBINS + bl] = s_res[c * BINS_PER_GRP + bl];
    }
}

extern "C" void kernel_launch(void* const* d_in, const int* in_sizes, int n_in,
                              void* d_out, int out_size) {
    const float* x    = (const float*)d_in[0];   // [B,256,50,50]
    const float* rois = (const float*)d_in[1];   // [N,5]
    float* out = (float*)d_out;                  // [N,256,7,7]

    const int N = in_sizes[1] / 5;
    const int B = in_sizes[0] / (C_TOT * HW);

    dim3 tgrid((HW + 31) / 32, C_TOT / 32, B);
    dim3 tblock(32, 8);
    transpose_in_kernel<<<tgrid, tblock>>>(x);

    dim3 ggrid(N, C_TOT / CH, BIN_SPLIT);        // (128, 2, 2) = 512 blocks
    roi_gather_kernel<<<ggrid, GTHREADS>>>(rois, out, N);
}